// round 10
// baseline (speedup 1.0000x reference)
#include <cuda_runtime.h>
#include <cuda_fp16.h>
#include <cstdint>

#define NN 50000
#define EE 1600000
#define GG 512
#define SCAN_BLKS ((NN + 1023) / 1024)   // 49

// ---------------------------------------------------------------------------
// Device scratch (static; no allocations anywhere)
// ---------------------------------------------------------------------------
__device__ int    g_deg[NN];
__device__ int    g_rowptr[NN + 1];
__device__ int    g_fill[NN];
__device__ int    g_col[EE];
__device__ int    g_gstart[GG + 1];
__device__ int    g_bsum[SCAN_BLKS];
__device__ int    g_boff[SCAN_BLKS];
__device__ float4 g_agg4[(size_t)NN * 32];   // [N,128] fp32
__device__ float4 g_h1_4[(size_t)NN * 32];   // [N,128] fp32
__device__ float4 g_h2_4[(size_t)NN * 64];   // [N,256] fp32
__device__ float4 g_y3_4[(size_t)NN * 32];   // [N,128] fp32
__device__ float4 g_z3_4[(size_t)NN * 32];   // [N,128] fp32
// fp16 mirrors of the three tensors that get aggregated (gather at 256B/edge)
__device__ __half2 g_xh [(size_t)NN * 64];   // [N,128] fp16
__device__ __half2 g_h1h[(size_t)NN * 64];
__device__ __half2 g_y3h[(size_t)NN * 64];

__device__ __forceinline__ const float* buf_ptr(int sel, const float* x) {
    switch (sel) {
        case 0: return (const float*)g_agg4;
        case 1: return (const float*)g_h1_4;
        case 2: return (const float*)g_h2_4;
        case 3: return (const float*)g_y3_4;
        case 4: return (const float*)g_z3_4;
        default: return x;
    }
}
__device__ __forceinline__ float* out_ptr(int sel) {
    switch (sel) {
        case 0: return (float*)g_agg4;
        case 1: return (float*)g_h1_4;
        case 2: return (float*)g_h2_4;
        case 3: return (float*)g_y3_4;
        default: return (float*)g_z3_4;
    }
}
__device__ __forceinline__ const __half2* hbuf_ptr(int sel) {
    switch (sel) {
        case 0: return g_xh;
        case 1: return g_h1h;
        default: return g_y3h;
    }
}
__device__ __forceinline__ __half2* hout_ptr(int sel) {
    switch (sel) {
        case 0: return g_xh;
        case 1: return g_h1h;
        default: return g_y3h;
    }
}

// ---------------------------------------------------------------------------
// fp16 mirror of x (one-shot convert)
// ---------------------------------------------------------------------------
__global__ void convert_x_kernel(const float* __restrict__ x) {
    int i = blockIdx.x * blockDim.x + threadIdx.x;   // float4 index
    if (i < NN * 32) {
        float4 v = *(const float4*)&x[i * 4];
        g_xh[i * 2 + 0] = __floats2half2_rn(v.x, v.y);
        g_xh[i * 2 + 1] = __floats2half2_rn(v.z, v.w);
    }
}

// ---------------------------------------------------------------------------
// CSR construction (int32 indices)
// ---------------------------------------------------------------------------
__global__ void zero_deg_kernel() {
    int i = blockIdx.x * blockDim.x + threadIdx.x;
    if (i < NN) g_deg[i] = 0;
}

__global__ void count_kernel(const int* __restrict__ dst) {
    int e = blockIdx.x * blockDim.x + threadIdx.x;
    if (e < EE) {
        int d = dst[e];
        if (d >= 0 && d < NN) atomicAdd(&g_deg[d], 1);
    }
}

// --- 3-phase parallel exclusive scan of g_deg -> g_rowptr, g_fill ----------
__global__ void block_reduce_kernel() {
    __shared__ int wsum[32];
    int tid = threadIdx.x, lane = tid & 31, wid = tid >> 5;
    int idx = blockIdx.x * 1024 + tid;
    int v = (idx < NN) ? g_deg[idx] : 0;
    int s = v;
    #pragma unroll
    for (int o = 16; o > 0; o >>= 1) s += __shfl_down_sync(0xFFFFFFFFu, s, o);
    if (lane == 0) wsum[wid] = s;
    __syncthreads();
    if (wid == 0) {
        int t = wsum[lane];
        #pragma unroll
        for (int o = 16; o > 0; o >>= 1) t += __shfl_down_sync(0xFFFFFFFFu, t, o);
        if (lane == 0) g_bsum[blockIdx.x] = t;
    }
}

__global__ void scan_bsums_kernel() {
    int tid = threadIdx.x;
    int lane = tid & 31, wid = tid >> 5;
    __shared__ int w0sum;
    int v = (tid < SCAN_BLKS) ? g_bsum[tid] : 0;
    int sc = v;
    #pragma unroll
    for (int o = 1; o < 32; o <<= 1) {
        int t = __shfl_up_sync(0xFFFFFFFFu, sc, o);
        if (lane >= o) sc += t;
    }
    if (tid == 31) w0sum = sc;
    __syncthreads();
    int excl = sc - v + (wid ? w0sum : 0);
    if (tid < SCAN_BLKS) g_boff[tid] = excl;
    if (tid == SCAN_BLKS - 1) g_rowptr[NN] = excl + v;
}

__global__ void block_scan_kernel() {
    __shared__ int wsum[32];
    int tid = threadIdx.x, lane = tid & 31, wid = tid >> 5;
    int idx = blockIdx.x * 1024 + tid;
    int v = (idx < NN) ? g_deg[idx] : 0;
    int sc = v;
    #pragma unroll
    for (int o = 1; o < 32; o <<= 1) {
        int t = __shfl_up_sync(0xFFFFFFFFu, sc, o);
        if (lane >= o) sc += t;
    }
    if (lane == 31) wsum[wid] = sc;
    __syncthreads();
    if (wid == 0) {
        int w = wsum[lane];
        int ws = w;
        #pragma unroll
        for (int o = 1; o < 32; o <<= 1) {
            int t = __shfl_up_sync(0xFFFFFFFFu, ws, o);
            if (lane >= o) ws += t;
        }
        wsum[lane] = ws - w;
    }
    __syncthreads();
    if (idx < NN) {
        int excl = g_boff[blockIdx.x] + wsum[wid] + sc - v;
        g_rowptr[idx] = excl;
        g_fill[idx]   = excl;
    }
}

__global__ void fill_kernel(const int* __restrict__ src,
                            const int* __restrict__ dst) {
    int e = blockIdx.x * blockDim.x + threadIdx.x;
    if (e < EE) {
        int d = dst[e];
        if (d >= 0 && d < NN) {
            int p = atomicAdd(&g_fill[d], 1);
            g_col[p] = src[e];
        }
    }
}

// ---------------------------------------------------------------------------
// fp16 aggregation (fp32 accum), edge loop unrolled x4 for MLP.
// ---------------------------------------------------------------------------
__global__ void aggregate_h_kernel(int feat_sel) {
    const __half2* feat = hbuf_ptr(feat_sel);
    int warp = (blockIdx.x * blockDim.x + threadIdx.x) >> 5;
    int lane = threadIdx.x & 31;
    if (warp >= NN) return;
    int s = g_rowptr[warp];
    int e = g_rowptr[warp + 1];
    float4 acc = make_float4(0.f, 0.f, 0.f, 0.f);
    int j = s;
    for (; j + 4 <= e; j += 4) {
        int c0 = g_col[j], c1 = g_col[j + 1], c2 = g_col[j + 2], c3 = g_col[j + 3];
        uint2 r0 = *(const uint2*)&feat[(size_t)c0 * 64 + lane * 2];
        uint2 r1 = *(const uint2*)&feat[(size_t)c1 * 64 + lane * 2];
        uint2 r2 = *(const uint2*)&feat[(size_t)c2 * 64 + lane * 2];
        uint2 r3 = *(const uint2*)&feat[(size_t)c3 * 64 + lane * 2];
        float2 a0 = __half22float2(*(__half2*)&r0.x), b0 = __half22float2(*(__half2*)&r0.y);
        float2 a1 = __half22float2(*(__half2*)&r1.x), b1 = __half22float2(*(__half2*)&r1.y);
        float2 a2 = __half22float2(*(__half2*)&r2.x), b2 = __half22float2(*(__half2*)&r2.y);
        float2 a3 = __half22float2(*(__half2*)&r3.x), b3 = __half22float2(*(__half2*)&r3.y);
        acc.x += (a0.x + a1.x) + (a2.x + a3.x);
        acc.y += (a0.y + a1.y) + (a2.y + a3.y);
        acc.z += (b0.x + b1.x) + (b2.x + b3.x);
        acc.w += (b0.y + b1.y) + (b2.y + b3.y);
    }
    for (; j < e; j++) {
        int c = g_col[j];
        uint2 raw = *(const uint2*)&feat[(size_t)c * 64 + lane * 2];
        float2 fa = __half22float2(*(__half2*)&raw.x);
        float2 fb = __half22float2(*(__half2*)&raw.y);
        acc.x += fa.x; acc.y += fa.y; acc.z += fb.x; acc.w += fb.y;
    }
    g_agg4[(size_t)warp * 32 + lane] = acc;
}

// ---------------------------------------------------------------------------
// fp16 tensor-core GEMM (m16n8k16), register-prefetch double buffering.
// 128x128 tile, BK=32, 8 warps (4x2), warp tile 32x64.
// A in smem as half2 [BM][18] (pitch 72B); B transposed [BN][36] halves.
// ---------------------------------------------------------------------------
__device__ __forceinline__ void mma_f16(float* c, const uint32_t* a,
                                        const uint32_t* b) {
    asm volatile(
        "mma.sync.aligned.m16n8k16.row.col.f32.f16.f16.f32 "
        "{%0,%1,%2,%3}, {%4,%5,%6,%7}, {%8,%9}, {%0,%1,%2,%3};"
        : "+f"(c[0]), "+f"(c[1]), "+f"(c[2]), "+f"(c[3])
        : "r"(a[0]), "r"(a[1]), "r"(a[2]), "r"(a[3]), "r"(b[0]), "r"(b[1]));
}

#define BM 128
#define BN 128
#define BK 32
#define APITCH 18   // half2 per A row (16 used + 2 pad) = 72B
#define BPITCH 36   // half per B_t row (32 used + 4 pad) = 72B

__device__ __forceinline__ void ldg_tile(
    const float* __restrict__ A, const float* __restrict__ W,
    int K, int Cout, int kt, int row0, int col0, int M, int tid,
    float4* Ar, float4* Br) {
    #pragma unroll
    for (int i = 0; i < 4; i++) {
        int lin = tid + i * 256;
        int r = lin >> 3, c4 = (lin & 7) << 2;
        int gr = row0 + r;
        Ar[i] = (gr < M) ? *(const float4*)&A[(size_t)gr * K + kt + c4]
                         : make_float4(0.f, 0.f, 0.f, 0.f);
    }
    #pragma unroll
    for (int i = 0; i < 4; i++) {
        int lin = tid + i * 256;
        int bk = lin >> 5, c4 = (lin & 31) << 2;
        Br[i] = *(const float4*)&W[(size_t)(kt + bk) * Cout + col0 + c4];
    }
}

__global__ void __launch_bounds__(256, 2)
gemm_tc_kernel(const float* __restrict__ x,
               int a0_sel, const float* __restrict__ W0, int K0,
               int a1_sel, const float* __restrict__ W1, int K1,
               const float* __restrict__ bias, int c_sel,
               int M, int Cout, int relu,
               const float* __restrict__ Wb, const float* __restrict__ biasb,
               int cb_sel, int hc_sel) {
    __shared__ __half2 As2[BM * APITCH];
    __shared__ __half  Bst[BN * BPITCH];

    int tid  = threadIdx.x;
    int wid  = tid >> 5, lane = tid & 31;
    int gid  = lane >> 2, tig = lane & 3;
    int wm   = wid & 3,  wn  = wid >> 2;
    int row0 = blockIdx.x * BM;
    int col0;
    if (Wb != nullptr) {             // dual-output: blockIdx.y picks W/bias/C
        col0 = 0;
        if (blockIdx.y == 1) { W0 = Wb; bias = biasb; c_sel = cb_sel; hc_sel = -1; }
    } else {
        col0 = blockIdx.y * BN;
    }

    float acc[2][8][4];
    #pragma unroll
    for (int i = 0; i < 2; i++)
        #pragma unroll
        for (int j = 0; j < 8; j++)
            #pragma unroll
            for (int k = 0; k < 4; k++) acc[i][j][k] = 0.f;

    const float* A0 = buf_ptr(a0_sel, x);
    const float* A1 = (a1_sel < 0) ? nullptr : buf_ptr(a1_sel, x);
    int T0 = K0 >> 5;
    int T1 = (a1_sel < 0) ? 0 : (K1 >> 5);
    int T  = T0 + T1;

    float4 Ar[4], Br[4];
    ldg_tile(A0, W0, K0, Cout, 0, row0, col0, M, tid, Ar, Br);

    #pragma unroll 1
    for (int t = 0; t < T; t++) {
        // stage A (fp16 convert; one 8B store per float4)
        #pragma unroll
        for (int i = 0; i < 4; i++) {
            int lin = tid + i * 256;
            int r = lin >> 3, c4 = (lin & 7) << 2;
            __half2 h0 = __floats2half2_rn(Ar[i].x, Ar[i].y);
            __half2 h1 = __floats2half2_rn(Ar[i].z, Ar[i].w);
            *(uint2*)&As2[r * APITCH + (c4 >> 1)] =
                make_uint2(*(uint32_t*)&h0, *(uint32_t*)&h1);
        }
        // stage B transposed: Bst[n][k]
        #pragma unroll
        for (int i = 0; i < 4; i++) {
            int lin = tid + i * 256;
            int bk = lin >> 5, c4 = (lin & 31) << 2;
            Bst[(c4 + 0) * BPITCH + bk] = __float2half_rn(Br[i].x);
            Bst[(c4 + 1) * BPITCH + bk] = __float2half_rn(Br[i].y);
            Bst[(c4 + 2) * BPITCH + bk] = __float2half_rn(Br[i].z);
            Bst[(c4 + 3) * BPITCH + bk] = __float2half_rn(Br[i].w);
        }
        __syncthreads();

        if (t + 1 < T) {
            int tn_ = t + 1;
            const float* A = (tn_ < T0) ? A0 : A1;
            const float* W = (tn_ < T0) ? W0 : W1;
            int K  = (tn_ < T0) ? K0 : K1;
            int kt = (tn_ < T0) ? tn_ * BK : (tn_ - T0) * BK;
            ldg_tile(A, W, K, Cout, kt, row0, col0, M, tid, Ar, Br);
        }

        #pragma unroll
        for (int ks = 0; ks < 2; ks++) {
            int k0  = ks * 16;       // half index
            int k0h = ks * 8;        // half2 index
            uint32_t af[2][4];
            #pragma unroll
            for (int mt = 0; mt < 2; mt++) {
                int r = wm * 32 + mt * 16 + gid;
                af[mt][0] = *(uint32_t*)&As2[(r    ) * APITCH + k0h + tig];
                af[mt][1] = *(uint32_t*)&As2[(r + 8) * APITCH + k0h + tig];
                af[mt][2] = *(uint32_t*)&As2[(r    ) * APITCH + k0h + 4 + tig];
                af[mt][3] = *(uint32_t*)&As2[(r + 8) * APITCH + k0h + 4 + tig];
            }
            uint32_t bf[8][2];
            #pragma unroll
            for (int nt = 0; nt < 8; nt++) {
                int c = wn * 64 + nt * 8 + gid;
                bf[nt][0] = *(uint32_t*)&Bst[c * BPITCH + k0 + tig * 2];
                bf[nt][1] = *(uint32_t*)&Bst[c * BPITCH + k0 + 8 + tig * 2];
            }
            #pragma unroll
            for (int mt = 0; mt < 2; mt++)
                #pragma unroll
                for (int nt = 0; nt < 8; nt++)
                    mma_f16(acc[mt][nt], af[mt], bf[nt]);
        }
        __syncthreads();
    }

    float* C = out_ptr(c_sel);
    __half2* Ch = (hc_sel >= 0) ? hout_ptr(hc_sel) : nullptr;
    #pragma unroll
    for (int mt = 0; mt < 2; mt++) {
        #pragma unroll
        for (int half_ = 0; half_ < 2; half_++) {
            int r = row0 + wm * 32 + mt * 16 + gid + half_ * 8;
            if (r < M) {
                #pragma unroll
                for (int nt = 0; nt < 8; nt++) {
                    int c = col0 + wn * 64 + nt * 8 + tig * 2;
                    float v0 = acc[mt][nt][half_ * 2 + 0];
                    float v1 = acc[mt][nt][half_ * 2 + 1];
                    if (bias) { v0 += bias[c]; v1 += bias[c + 1]; }
                    if (relu) { v0 = fmaxf(v0, 0.f); v1 = fmaxf(v1, 0.f); }
                    *(float2*)&C[(size_t)r * Cout + c] = make_float2(v0, v1);
                    if (Ch) Ch[((size_t)r * Cout + c) >> 1] =
                        __floats2half2_rn(v0, v1);
                }
            }
        }
    }
}

// ---------------------------------------------------------------------------
// Graph segment boundaries via binary search over sorted batch (int32)
// ---------------------------------------------------------------------------
__global__ void gstart_kernel(const int* __restrict__ batch) {
    int g = blockIdx.x * blockDim.x + threadIdx.x;
    if (g > GG) return;
    int lo = 0, hi = NN;
    while (lo < hi) {
        int mid = (lo + hi) >> 1;
        if (batch[mid] < g) lo = mid + 1; else hi = mid;
    }
    g_gstart[g] = lo;
}

// ---------------------------------------------------------------------------
// Pool (mean over graph) + 2-layer MLP head. One 128-thread block per graph.
// ---------------------------------------------------------------------------
__global__ void pool_head_kernel(const float* __restrict__ W1,
                                 const float* __restrict__ b1,
                                 const float* __restrict__ W2,
                                 const float* __restrict__ b2,
                                 float* __restrict__ out) {
    int g = blockIdx.x;
    int c = threadIdx.x;  // 0..127
    int s = g_gstart[g];
    int e = g_gstart[g + 1];
    const float* agg = (const float*)g_agg4;
    const float* z3  = (const float*)g_z3_4;
    float acc = 0.f;
    for (int n = s; n < e; n++)
        acc += agg[(size_t)n * 128 + c] + z3[(size_t)n * 128 + c];
    float cnt = (float)((e - s) > 1 ? (e - s) : 1);
    __shared__ float p[128];
    __shared__ float t[40];
    p[c] = acc / cnt;
    __syncthreads();
    if (c < 40) {
        float tt = b1[c];
        #pragma unroll 4
        for (int k = 0; k < 128; k++) tt += p[k] * W1[k * 40 + c];
        t[c] = tt;
    }
    __syncthreads();
    if (c < 10) {
        float o = b2[c];
        #pragma unroll
        for (int k = 0; k < 40; k++) o += t[k] * W2[k * 10 + c];
        out[g * 10 + c] = o;
    }
}

// ---------------------------------------------------------------------------
// Launch: ONLY kernel launches.
// ---------------------------------------------------------------------------
extern "C" void kernel_launch(void* const* d_in, const int* in_sizes, int n_in,
                              void* d_out, int out_size) {
    const float* x     = (const float*)d_in[0];
    const int*   ei    = (const int*)d_in[1];
    const int*   batch = (const int*)d_in[2];
    const float* Wr1 = (const float*)d_in[3];
    const float* br1 = (const float*)d_in[4];
    const float* Wo1 = (const float*)d_in[5];
    const float* Wr2 = (const float*)d_in[6];
    const float* br2 = (const float*)d_in[7];
    const float* Wo2 = (const float*)d_in[8];
    const float* Wr3 = (const float*)d_in[9];
    const float* br3 = (const float*)d_in[10];
    const float* Wo3 = (const float*)d_in[11];
    const float* W1  = (const float*)d_in[12];
    const float* b1  = (const float*)d_in[13];
    const float* W2  = (const float*)d_in[14];
    const float* b2  = (const float*)d_in[15];
    float* out = (float*)d_out;

    const int* srcp = ei;
    const int* dstp = ei + EE;

    const int EB = (EE + 255) / 256;
    const int AGGB = (NN * 32 + 255) / 256;
    dim3 g1((NN + 127) / 128, 1);
    dim3 g2((NN + 127) / 128, 2);

    // CSR build + x fp16 mirror
    zero_deg_kernel<<<(NN + 255) / 256, 256>>>();
    convert_x_kernel<<<(NN * 32 + 255) / 256, 256>>>(x);
    count_kernel<<<EB, 256>>>(dstp);
    block_reduce_kernel<<<SCAN_BLKS, 1024>>>();
    scan_bsums_kernel<<<1, 64>>>();
    block_scan_kernel<<<SCAN_BLKS, 1024>>>();
    fill_kernel<<<EB, 256>>>(srcp, dstp);
    gstart_kernel<<<1, 1024>>>(batch);

    // Layer 1: agg = A(x_h); h1 = relu(agg@Wr1 + x@Wo1 + br1)  (+h1 fp16 mirror)
    aggregate_h_kernel<<<AGGB, 256>>>(0);
    gemm_tc_kernel<<<g1, 256>>>(x, 0, Wr1, 128, 5, Wo1, 128, br1, 1,
                                NN, 128, 1, nullptr, nullptr, 0, 1);

    // Layer 2: agg = A(h1_h); h2 = relu(agg@Wr2 + h1@Wo2 + br2)
    aggregate_h_kernel<<<AGGB, 256>>>(1);
    gemm_tc_kernel<<<g2, 256>>>(x, 0, Wr2, 128, 1, Wo2, 128, br2, 2,
                                NN, 256, 1, nullptr, nullptr, 0, -1);

    // Layer 3 (matmul-first, dual-output): y3 = h2@Wr3 (+fp16 mirror);
    // z3 = h2@Wo3 + br3
    gemm_tc_kernel<<<g2, 256>>>(x, 2, Wr3, 256, -1, nullptr, 0, nullptr, 3,
                                NN, 128, 0, Wo3, br3, 4, 2);

    // agg = A(y3_h), then pool + head
    aggregate_h_kernel<<<AGGB, 256>>>(2);
    pool_head_kernel<<<GG, 128>>>(W1, b1, W2, b2, out);
}

// round 11
// speedup vs baseline: 1.2761x; 1.2761x over previous
#include <cuda_runtime.h>
#include <cuda_fp16.h>
#include <cstdint>

#define NN 50000
#define EE 1600000
#define GG 512
#define SCAN_BLKS ((NN + 1023) / 1024)   // 49

// ---------------------------------------------------------------------------
// Device scratch (static; no allocations anywhere)
// ---------------------------------------------------------------------------
__device__ int    g_deg[NN];
__device__ int    g_rowptr[NN + 1];
__device__ int    g_fill[NN];
__device__ int    g_col[EE];
__device__ int    g_gstart[GG + 1];
__device__ int    g_bsum[SCAN_BLKS];
__device__ int    g_boff[SCAN_BLKS];
__device__ float4 g_agg4[(size_t)NN * 32];   // [N,128] fp32
__device__ float4 g_h1_4[(size_t)NN * 32];   // [N,128] fp32
__device__ float4 g_h2_4[(size_t)NN * 64];   // [N,256] fp32
__device__ float4 g_y3_4[(size_t)NN * 32];   // [N,128] fp32
__device__ float4 g_z3_4[(size_t)NN * 32];   // [N,128] fp32
// fp16 mirrors of the three tensors that get aggregated (gather at 256B/edge)
__device__ __half2 g_xh [(size_t)NN * 64];   // [N,128] fp16
__device__ __half2 g_h1h[(size_t)NN * 64];
__device__ __half2 g_y3h[(size_t)NN * 64];

__device__ __forceinline__ const float* buf_ptr(int sel, const float* x) {
    switch (sel) {
        case 0: return (const float*)g_agg4;
        case 1: return (const float*)g_h1_4;
        case 2: return (const float*)g_h2_4;
        case 3: return (const float*)g_y3_4;
        case 4: return (const float*)g_z3_4;
        default: return x;
    }
}
__device__ __forceinline__ float* out_ptr(int sel) {
    switch (sel) {
        case 0: return (float*)g_agg4;
        case 1: return (float*)g_h1_4;
        case 2: return (float*)g_h2_4;
        case 3: return (float*)g_y3_4;
        default: return (float*)g_z3_4;
    }
}
__device__ __forceinline__ const __half2* hbuf_ptr(int sel) {
    switch (sel) {
        case 0: return g_xh;
        case 1: return g_h1h;
        default: return g_y3h;
    }
}
__device__ __forceinline__ __half2* hout_ptr(int sel) {
    switch (sel) {
        case 0: return g_xh;
        case 1: return g_h1h;
        default: return g_y3h;
    }
}

// ---------------------------------------------------------------------------
// fp16 mirror of x (one-shot convert)
// ---------------------------------------------------------------------------
__global__ void convert_x_kernel(const float* __restrict__ x) {
    int i = blockIdx.x * blockDim.x + threadIdx.x;   // float4 index
    if (i < NN * 32) {
        float4 v = *(const float4*)&x[i * 4];
        g_xh[i * 2 + 0] = __floats2half2_rn(v.x, v.y);
        g_xh[i * 2 + 1] = __floats2half2_rn(v.z, v.w);
    }
}

// ---------------------------------------------------------------------------
// CSR construction (int32 indices)
// ---------------------------------------------------------------------------
__global__ void zero_deg_kernel() {
    int i = blockIdx.x * blockDim.x + threadIdx.x;
    if (i < NN) g_deg[i] = 0;
}

__global__ void count_kernel(const int* __restrict__ dst) {
    int e = blockIdx.x * blockDim.x + threadIdx.x;
    if (e < EE) {
        int d = dst[e];
        if (d >= 0 && d < NN) atomicAdd(&g_deg[d], 1);
    }
}

// --- 3-phase parallel exclusive scan of g_deg -> g_rowptr, g_fill ----------
__global__ void block_reduce_kernel() {
    __shared__ int wsum[32];
    int tid = threadIdx.x, lane = tid & 31, wid = tid >> 5;
    int idx = blockIdx.x * 1024 + tid;
    int v = (idx < NN) ? g_deg[idx] : 0;
    int s = v;
    #pragma unroll
    for (int o = 16; o > 0; o >>= 1) s += __shfl_down_sync(0xFFFFFFFFu, s, o);
    if (lane == 0) wsum[wid] = s;
    __syncthreads();
    if (wid == 0) {
        int t = wsum[lane];
        #pragma unroll
        for (int o = 16; o > 0; o >>= 1) t += __shfl_down_sync(0xFFFFFFFFu, t, o);
        if (lane == 0) g_bsum[blockIdx.x] = t;
    }
}

__global__ void scan_bsums_kernel() {
    int tid = threadIdx.x;
    int lane = tid & 31, wid = tid >> 5;
    __shared__ int w0sum;
    int v = (tid < SCAN_BLKS) ? g_bsum[tid] : 0;
    int sc = v;
    #pragma unroll
    for (int o = 1; o < 32; o <<= 1) {
        int t = __shfl_up_sync(0xFFFFFFFFu, sc, o);
        if (lane >= o) sc += t;
    }
    if (tid == 31) w0sum = sc;
    __syncthreads();
    int excl = sc - v + (wid ? w0sum : 0);
    if (tid < SCAN_BLKS) g_boff[tid] = excl;
    if (tid == SCAN_BLKS - 1) g_rowptr[NN] = excl + v;
}

__global__ void block_scan_kernel() {
    __shared__ int wsum[32];
    int tid = threadIdx.x, lane = tid & 31, wid = tid >> 5;
    int idx = blockIdx.x * 1024 + tid;
    int v = (idx < NN) ? g_deg[idx] : 0;
    int sc = v;
    #pragma unroll
    for (int o = 1; o < 32; o <<= 1) {
        int t = __shfl_up_sync(0xFFFFFFFFu, sc, o);
        if (lane >= o) sc += t;
    }
    if (lane == 31) wsum[wid] = sc;
    __syncthreads();
    if (wid == 0) {
        int w = wsum[lane];
        int ws = w;
        #pragma unroll
        for (int o = 1; o < 32; o <<= 1) {
            int t = __shfl_up_sync(0xFFFFFFFFu, ws, o);
            if (lane >= o) ws += t;
        }
        wsum[lane] = ws - w;
    }
    __syncthreads();
    if (idx < NN) {
        int excl = g_boff[blockIdx.x] + wsum[wid] + sc - v;
        g_rowptr[idx] = excl;
        g_fill[idx]   = excl;
    }
}

__global__ void fill_kernel(const int* __restrict__ src,
                            const int* __restrict__ dst) {
    int e = blockIdx.x * blockDim.x + threadIdx.x;
    if (e < EE) {
        int d = dst[e];
        if (d >= 0 && d < NN) {
            int p = atomicAdd(&g_fill[d], 1);
            g_col[p] = src[e];
        }
    }
}

// ---------------------------------------------------------------------------
// fp16 aggregation (fp32 accum). One warp per node (R9 form).
// ---------------------------------------------------------------------------
__global__ void aggregate_h_kernel(int feat_sel) {
    const __half2* feat = hbuf_ptr(feat_sel);
    int warp = (blockIdx.x * blockDim.x + threadIdx.x) >> 5;
    int lane = threadIdx.x & 31;
    if (warp >= NN) return;
    int s = g_rowptr[warp];
    int e = g_rowptr[warp + 1];
    float4 acc = make_float4(0.f, 0.f, 0.f, 0.f);
    for (int j = s; j < e; j++) {
        int c = g_col[j];
        uint2 raw = *(const uint2*)&feat[(size_t)c * 64 + lane * 2];
        float2 fa = __half22float2(*(__half2*)&raw.x);
        float2 fb = __half22float2(*(__half2*)&raw.y);
        acc.x += fa.x; acc.y += fa.y; acc.z += fb.x; acc.w += fb.y;
    }
    g_agg4[(size_t)warp * 32 + lane] = acc;
}

// ---------------------------------------------------------------------------
// fp16 tensor-core GEMM (m16n8k16) with ldmatrix fragment loads.
// 128x128 tile, BK=32, 8 warps (4x2), warp tile 32x64.
// A: [BM][APITCH] halves (pitch 80B); B: [BK][BPITCH] halves (pitch 272B) —
// natural orientation, 8B half2 staging stores; ldmatrix/.trans for frags.
// ---------------------------------------------------------------------------
__device__ __forceinline__ void mma_f16(float* c, const uint32_t* a,
                                        const uint32_t* b) {
    asm volatile(
        "mma.sync.aligned.m16n8k16.row.col.f32.f16.f16.f32 "
        "{%0,%1,%2,%3}, {%4,%5,%6,%7}, {%8,%9}, {%0,%1,%2,%3};"
        : "+f"(c[0]), "+f"(c[1]), "+f"(c[2]), "+f"(c[3])
        : "r"(a[0]), "r"(a[1]), "r"(a[2]), "r"(a[3]), "r"(b[0]), "r"(b[1]));
}
__device__ __forceinline__ uint32_t smem_u32(const void* p) {
    return (uint32_t)__cvta_generic_to_shared(p);
}
__device__ __forceinline__ void ldsm_x4(uint32_t* r, uint32_t addr) {
    asm volatile("ldmatrix.sync.aligned.m8n8.x4.shared.b16 {%0,%1,%2,%3}, [%4];"
                 : "=r"(r[0]), "=r"(r[1]), "=r"(r[2]), "=r"(r[3]) : "r"(addr));
}
__device__ __forceinline__ void ldsm_x4_trans(uint32_t* r, uint32_t addr) {
    asm volatile("ldmatrix.sync.aligned.m8n8.x4.trans.shared.b16 {%0,%1,%2,%3}, [%4];"
                 : "=r"(r[0]), "=r"(r[1]), "=r"(r[2]), "=r"(r[3]) : "r"(addr));
}

#define BM 128
#define BN 128
#define BK 32
#define APITCH 40    // halves per A row (32 used + 8 pad) = 80B
#define BPITCH 136   // halves per B row (128 used + 8 pad) = 272B

__device__ __forceinline__ void ldg_tile(
    const float* __restrict__ A, const float* __restrict__ W,
    int K, int Cout, int kt, int row0, int col0, int M, int tid,
    float4* Ar, float4* Br) {
    #pragma unroll
    for (int i = 0; i < 4; i++) {
        int lin = tid + i * 256;
        int r = lin >> 3, c4 = (lin & 7) << 2;
        int gr = row0 + r;
        Ar[i] = (gr < M) ? *(const float4*)&A[(size_t)gr * K + kt + c4]
                         : make_float4(0.f, 0.f, 0.f, 0.f);
    }
    #pragma unroll
    for (int i = 0; i < 4; i++) {
        int lin = tid + i * 256;
        int bk = lin >> 5, c4 = (lin & 31) << 2;
        Br[i] = *(const float4*)&W[(size_t)(kt + bk) * Cout + col0 + c4];
    }
}

__global__ void __launch_bounds__(256, 2)
gemm_tc_kernel(const float* __restrict__ x,
               int a0_sel, const float* __restrict__ W0, int K0,
               int a1_sel, const float* __restrict__ W1, int K1,
               const float* __restrict__ bias, int c_sel,
               int M, int Cout, int relu,
               const float* __restrict__ Wb, const float* __restrict__ biasb,
               int cb_sel, int hc_sel) {
    __shared__ __half As[BM * APITCH];
    __shared__ __half Bs[BK * BPITCH];

    int tid  = threadIdx.x;
    int wid  = tid >> 5, lane = tid & 31;
    int gid  = lane >> 2, tig = lane & 3;
    int wm   = wid & 3,  wn  = wid >> 2;
    int row0 = blockIdx.x * BM;
    int col0;
    if (Wb != nullptr) {             // dual-output: blockIdx.y picks W/bias/C
        col0 = 0;
        if (blockIdx.y == 1) { W0 = Wb; bias = biasb; c_sel = cb_sel; hc_sel = -1; }
    } else {
        col0 = blockIdx.y * BN;
    }

    // ldmatrix per-lane source row/col decomposition
    int lr  = lane & 7;             // row within 8x8 tile
    int g1_ = (lane >> 3) & 1;      // +8 rows for matrices 1,3
    int g2_ = lane >> 4;            // +8 cols for matrices 2,3

    float acc[2][8][4];
    #pragma unroll
    for (int i = 0; i < 2; i++)
        #pragma unroll
        for (int j = 0; j < 8; j++)
            #pragma unroll
            for (int k = 0; k < 4; k++) acc[i][j][k] = 0.f;

    const float* A0 = buf_ptr(a0_sel, x);
    const float* A1 = (a1_sel < 0) ? nullptr : buf_ptr(a1_sel, x);
    int T0 = K0 >> 5;
    int T1 = (a1_sel < 0) ? 0 : (K1 >> 5);
    int T  = T0 + T1;

    float4 Ar[4], Br[4];
    ldg_tile(A0, W0, K0, Cout, 0, row0, col0, M, tid, Ar, Br);

    #pragma unroll 1
    for (int t = 0; t < T; t++) {
        // stage A [BM][BK] (half2 8B stores; two-phase, conflict-free)
        #pragma unroll
        for (int i = 0; i < 4; i++) {
            int lin = tid + i * 256;
            int r = lin >> 3, c4 = (lin & 7) << 2;
            __half2 h0 = __floats2half2_rn(Ar[i].x, Ar[i].y);
            __half2 h1 = __floats2half2_rn(Ar[i].z, Ar[i].w);
            *(uint2*)&As[r * APITCH + c4] =
                make_uint2(*(uint32_t*)&h0, *(uint32_t*)&h1);
        }
        // stage B [BK][BN] natural orientation
        #pragma unroll
        for (int i = 0; i < 4; i++) {
            int lin = tid + i * 256;
            int bk = lin >> 5, c4 = (lin & 31) << 2;
            __half2 h0 = __floats2half2_rn(Br[i].x, Br[i].y);
            __half2 h1 = __floats2half2_rn(Br[i].z, Br[i].w);
            *(uint2*)&Bs[bk * BPITCH + c4] =
                make_uint2(*(uint32_t*)&h0, *(uint32_t*)&h1);
        }
        __syncthreads();

        if (t + 1 < T) {
            int tn_ = t + 1;
            const float* A = (tn_ < T0) ? A0 : A1;
            const float* W = (tn_ < T0) ? W0 : W1;
            int K  = (tn_ < T0) ? K0 : K1;
            int kt = (tn_ < T0) ? tn_ * BK : (tn_ - T0) * BK;
            ldg_tile(A, W, K, Cout, kt, row0, col0, M, tid, Ar, Br);
        }

        #pragma unroll
        for (int ks = 0; ks < 2; ks++) {
            int k0 = ks * 16;
            uint32_t af[2][4];
            #pragma unroll
            for (int mt = 0; mt < 2; mt++) {
                int row = wm * 32 + mt * 16 + lr + g1_ * 8;
                int col = k0 + g2_ * 8;
                ldsm_x4(af[mt], smem_u32(&As[row * APITCH + col]));
            }
            uint32_t bf[8][2];
            #pragma unroll
            for (int np = 0; np < 4; np++) {
                int row = k0 + lr + g1_ * 8;
                int col = wn * 64 + np * 16 + g2_ * 8;
                uint32_t tmp[4];
                ldsm_x4_trans(tmp, smem_u32(&Bs[row * BPITCH + col]));
                bf[np * 2    ][0] = tmp[0];
                bf[np * 2    ][1] = tmp[1];
                bf[np * 2 + 1][0] = tmp[2];
                bf[np * 2 + 1][1] = tmp[3];
            }
            #pragma unroll
            for (int mt = 0; mt < 2; mt++)
                #pragma unroll
                for (int nt = 0; nt < 8; nt++)
                    mma_f16(acc[mt][nt], af[mt], bf[nt]);
        }
        __syncthreads();
    }

    float* C = out_ptr(c_sel);
    __half2* Ch = (hc_sel >= 0) ? hout_ptr(hc_sel) : nullptr;
    #pragma unroll
    for (int mt = 0; mt < 2; mt++) {
        #pragma unroll
        for (int half_ = 0; half_ < 2; half_++) {
            int r = row0 + wm * 32 + mt * 16 + gid + half_ * 8;
            if (r < M) {
                #pragma unroll
                for (int nt = 0; nt < 8; nt++) {
                    int c = col0 + wn * 64 + nt * 8 + tig * 2;
                    float v0 = acc[mt][nt][half_ * 2 + 0];
                    float v1 = acc[mt][nt][half_ * 2 + 1];
                    if (bias) { v0 += bias[c]; v1 += bias[c + 1]; }
                    if (relu) { v0 = fmaxf(v0, 0.f); v1 = fmaxf(v1, 0.f); }
                    *(float2*)&C[(size_t)r * Cout + c] = make_float2(v0, v1);
                    if (Ch) Ch[((size_t)r * Cout + c) >> 1] =
                        __floats2half2_rn(v0, v1);
                }
            }
        }
    }
}

// ---------------------------------------------------------------------------
// Graph segment boundaries via binary search over sorted batch (int32)
// ---------------------------------------------------------------------------
__global__ void gstart_kernel(const int* __restrict__ batch) {
    int g = blockIdx.x * blockDim.x + threadIdx.x;
    if (g > GG) return;
    int lo = 0, hi = NN;
    while (lo < hi) {
        int mid = (lo + hi) >> 1;
        if (batch[mid] < g) lo = mid + 1; else hi = mid;
    }
    g_gstart[g] = lo;
}

// ---------------------------------------------------------------------------
// Pool (mean over graph) + 2-layer MLP head. One 128-thread block per graph.
// ---------------------------------------------------------------------------
__global__ void pool_head_kernel(const float* __restrict__ W1,
                                 const float* __restrict__ b1,
                                 const float* __restrict__ W2,
                                 const float* __restrict__ b2,
                                 float* __restrict__ out) {
    int g = blockIdx.x;
    int c = threadIdx.x;  // 0..127
    int s = g_gstart[g];
    int e = g_gstart[g + 1];
    const float* agg = (const float*)g_agg4;
    const float* z3  = (const float*)g_z3_4;
    float acc = 0.f;
    for (int n = s; n < e; n++)
        acc += agg[(size_t)n * 128 + c] + z3[(size_t)n * 128 + c];
    float cnt = (float)((e - s) > 1 ? (e - s) : 1);
    __shared__ float p[128];
    __shared__ float t[40];
    p[c] = acc / cnt;
    __syncthreads();
    if (c < 40) {
        float tt = b1[c];
        #pragma unroll 4
        for (int k = 0; k < 128; k++) tt += p[k] * W1[k * 40 + c];
        t[c] = tt;
    }
    __syncthreads();
    if (c < 10) {
        float o = b2[c];
        #pragma unroll
        for (int k = 0; k < 40; k++) o += t[k] * W2[k * 10 + c];
        out[g * 10 + c] = o;
    }
}

// ---------------------------------------------------------------------------
// Launch: ONLY kernel launches.
// ---------------------------------------------------------------------------
extern "C" void kernel_launch(void* const* d_in, const int* in_sizes, int n_in,
                              void* d_out, int out_size) {
    const float* x     = (const float*)d_in[0];
    const int*   ei    = (const int*)d_in[1];
    const int*   batch = (const int*)d_in[2];
    const float* Wr1 = (const float*)d_in[3];
    const float* br1 = (const float*)d_in[4];
    const float* Wo1 = (const float*)d_in[5];
    const float* Wr2 = (const float*)d_in[6];
    const float* br2 = (const float*)d_in[7];
    const float* Wo2 = (const float*)d_in[8];
    const float* Wr3 = (const float*)d_in[9];
    const float* br3 = (const float*)d_in[10];
    const float* Wo3 = (const float*)d_in[11];
    const float* W1  = (const float*)d_in[12];
    const float* b1  = (const float*)d_in[13];
    const float* W2  = (const float*)d_in[14];
    const float* b2  = (const float*)d_in[15];
    float* out = (float*)d_out;

    const int* srcp = ei;
    const int* dstp = ei + EE;

    const int EB = (EE + 255) / 256;
    const int AGGB = (NN * 32 + 255) / 256;
    dim3 g1((NN + 127) / 128, 1);
    dim3 g2((NN + 127) / 128, 2);

    // CSR build + x fp16 mirror
    zero_deg_kernel<<<(NN + 255) / 256, 256>>>();
    convert_x_kernel<<<(NN * 32 + 255) / 256, 256>>>(x);
    count_kernel<<<EB, 256>>>(dstp);
    block_reduce_kernel<<<SCAN_BLKS, 1024>>>();
    scan_bsums_kernel<<<1, 64>>>();
    block_scan_kernel<<<SCAN_BLKS, 1024>>>();
    fill_kernel<<<EB, 256>>>(srcp, dstp);
    gstart_kernel<<<1, 1024>>>(batch);

    // Layer 1: agg = A(x_h); h1 = relu(agg@Wr1 + x@Wo1 + br1)  (+h1 fp16 mirror)
    aggregate_h_kernel<<<AGGB, 256>>>(0);
    gemm_tc_kernel<<<g1, 256>>>(x, 0, Wr1, 128, 5, Wo1, 128, br1, 1,
                                NN, 128, 1, nullptr, nullptr, 0, 1);

    // Layer 2: agg = A(h1_h); h2 = relu(agg@Wr2 + h1@Wo2 + br2)
    aggregate_h_kernel<<<AGGB, 256>>>(1);
    gemm_tc_kernel<<<g2, 256>>>(x, 0, Wr2, 128, 1, Wo2, 128, br2, 2,
                                NN, 256, 1, nullptr, nullptr, 0, -1);

    // Layer 3 (matmul-first, dual-output): y3 = h2@Wr3 (+fp16 mirror);
    // z3 = h2@Wo3 + br3
    gemm_tc_kernel<<<g2, 256>>>(x, 2, Wr3, 256, -1, nullptr, 0, nullptr, 3,
                                NN, 128, 0, Wo3, br3, 4, 2);

    // agg = A(y3_h), then pool + head
    aggregate_h_kernel<<<AGGB, 256>>>(2);
    pool_head_kernel<<<GG, 128>>>(W1, b1, W2, b2, out);
}

// round 12
// speedup vs baseline: 1.3946x; 1.0929x over previous
#include <cuda_runtime.h>
#include <cuda_fp16.h>
#include <cstdint>

#define NN 50000
#define EE 1600000
#define GG 512
#define SCAN_BLKS ((NN + 1023) / 1024)   // 49

// ---------------------------------------------------------------------------
// Device scratch (static; no allocations anywhere).
// ALL intermediate feature tensors are fp16-only (uint4 arrays => 16B aligned).
// ---------------------------------------------------------------------------
__device__ int   g_deg[NN];
__device__ int   g_rowptr[NN + 1];
__device__ int   g_fill[NN];
__device__ int   g_col[EE];
__device__ int   g_gstart[GG + 1];
__device__ int   g_bsum[SCAN_BLKS];
__device__ int   g_boff[SCAN_BLKS];
__device__ uint4 g_xh4 [(size_t)NN * 16];   // x   [N,128] fp16
__device__ uint4 g_aggh4[(size_t)NN * 16];  // agg [N,128] fp16
__device__ uint4 g_h1h4[(size_t)NN * 16];   // h1  [N,128] fp16
__device__ uint4 g_h2h4[(size_t)NN * 32];   // h2  [N,256] fp16
__device__ uint4 g_y3h4[(size_t)NN * 16];   // y3  [N,128] fp16
__device__ uint4 g_z3h4[(size_t)NN * 16];   // z3  [N,128] fp16

__device__ __forceinline__ const __half* hbuf(int sel) {
    switch (sel) {
        case 0: return (const __half*)g_xh4;
        case 1: return (const __half*)g_aggh4;
        case 2: return (const __half*)g_h1h4;
        case 3: return (const __half*)g_h2h4;
        case 4: return (const __half*)g_y3h4;
        default: return (const __half*)g_z3h4;
    }
}
__device__ __forceinline__ __half2* hout(int sel) {
    switch (sel) {
        case 1: return (__half2*)g_aggh4;
        case 2: return (__half2*)g_h1h4;
        case 3: return (__half2*)g_h2h4;
        case 4: return (__half2*)g_y3h4;
        default: return (__half2*)g_z3h4;
    }
}

// ---------------------------------------------------------------------------
// fp16 mirror of x (one-shot convert; 8 floats -> one uint4 of 8 halves)
// ---------------------------------------------------------------------------
__global__ void convert_x_kernel(const float* __restrict__ x) {
    int i = blockIdx.x * blockDim.x + threadIdx.x;   // uint4 index
    if (i < NN * 16) {
        float4 v0 = *(const float4*)&x[i * 8];
        float4 v1 = *(const float4*)&x[i * 8 + 4];
        __half2 h0 = __floats2half2_rn(v0.x, v0.y);
        __half2 h1 = __floats2half2_rn(v0.z, v0.w);
        __half2 h2 = __floats2half2_rn(v1.x, v1.y);
        __half2 h3 = __floats2half2_rn(v1.z, v1.w);
        g_xh4[i] = make_uint4(*(uint32_t*)&h0, *(uint32_t*)&h1,
                              *(uint32_t*)&h2, *(uint32_t*)&h3);
    }
}

// ---------------------------------------------------------------------------
// CSR construction (int32 indices)
// ---------------------------------------------------------------------------
__global__ void zero_deg_kernel() {
    int i = blockIdx.x * blockDim.x + threadIdx.x;
    if (i < NN) g_deg[i] = 0;
}

__global__ void count_kernel(const int* __restrict__ dst) {
    int e = blockIdx.x * blockDim.x + threadIdx.x;
    if (e < EE) {
        int d = dst[e];
        if (d >= 0 && d < NN) atomicAdd(&g_deg[d], 1);
    }
}

__global__ void block_reduce_kernel() {
    __shared__ int wsum[32];
    int tid = threadIdx.x, lane = tid & 31, wid = tid >> 5;
    int idx = blockIdx.x * 1024 + tid;
    int v = (idx < NN) ? g_deg[idx] : 0;
    int s = v;
    #pragma unroll
    for (int o = 16; o > 0; o >>= 1) s += __shfl_down_sync(0xFFFFFFFFu, s, o);
    if (lane == 0) wsum[wid] = s;
    __syncthreads();
    if (wid == 0) {
        int t = wsum[lane];
        #pragma unroll
        for (int o = 16; o > 0; o >>= 1) t += __shfl_down_sync(0xFFFFFFFFu, t, o);
        if (lane == 0) g_bsum[blockIdx.x] = t;
    }
}

__global__ void scan_bsums_kernel() {
    int tid = threadIdx.x;
    int lane = tid & 31, wid = tid >> 5;
    __shared__ int w0sum;
    int v = (tid < SCAN_BLKS) ? g_bsum[tid] : 0;
    int sc = v;
    #pragma unroll
    for (int o = 1; o < 32; o <<= 1) {
        int t = __shfl_up_sync(0xFFFFFFFFu, sc, o);
        if (lane >= o) sc += t;
    }
    if (tid == 31) w0sum = sc;
    __syncthreads();
    int excl = sc - v + (wid ? w0sum : 0);
    if (tid < SCAN_BLKS) g_boff[tid] = excl;
    if (tid == SCAN_BLKS - 1) g_rowptr[NN] = excl + v;
}

__global__ void block_scan_kernel() {
    __shared__ int wsum[32];
    int tid = threadIdx.x, lane = tid & 31, wid = tid >> 5;
    int idx = blockIdx.x * 1024 + tid;
    int v = (idx < NN) ? g_deg[idx] : 0;
    int sc = v;
    #pragma unroll
    for (int o = 1; o < 32; o <<= 1) {
        int t = __shfl_up_sync(0xFFFFFFFFu, sc, o);
        if (lane >= o) sc += t;
    }
    if (lane == 31) wsum[wid] = sc;
    __syncthreads();
    if (wid == 0) {
        int w = wsum[lane];
        int ws = w;
        #pragma unroll
        for (int o = 1; o < 32; o <<= 1) {
            int t = __shfl_up_sync(0xFFFFFFFFu, ws, o);
            if (lane >= o) ws += t;
        }
        wsum[lane] = ws - w;
    }
    __syncthreads();
    if (idx < NN) {
        int excl = g_boff[blockIdx.x] + wsum[wid] + sc - v;
        g_rowptr[idx] = excl;
        g_fill[idx]   = excl;
    }
}

__global__ void fill_kernel(const int* __restrict__ src,
                            const int* __restrict__ dst) {
    int e = blockIdx.x * blockDim.x + threadIdx.x;
    if (e < EE) {
        int d = dst[e];
        if (d >= 0 && d < NN) {
            int p = atomicAdd(&g_fill[d], 1);
            g_col[p] = src[e];
        }
    }
}

// ---------------------------------------------------------------------------
// fp16 aggregation (fp32 accum, fp16 output). One warp per node.
// ---------------------------------------------------------------------------
__global__ void aggregate_h_kernel(int feat_sel) {
    const __half2* feat = (const __half2*)hbuf(feat_sel);
    int warp = (blockIdx.x * blockDim.x + threadIdx.x) >> 5;
    int lane = threadIdx.x & 31;
    if (warp >= NN) return;
    int s = g_rowptr[warp];
    int e = g_rowptr[warp + 1];
    float4 acc = make_float4(0.f, 0.f, 0.f, 0.f);
    for (int j = s; j < e; j++) {
        int c = g_col[j];
        uint2 raw = *(const uint2*)&feat[(size_t)c * 64 + lane * 2];
        float2 fa = __half22float2(*(__half2*)&raw.x);
        float2 fb = __half22float2(*(__half2*)&raw.y);
        acc.x += fa.x; acc.y += fa.y; acc.z += fb.x; acc.w += fb.y;
    }
    __half2 o0 = __floats2half2_rn(acc.x, acc.y);
    __half2 o1 = __floats2half2_rn(acc.z, acc.w);
    *(uint2*)&((__half2*)g_aggh4)[(size_t)warp * 64 + lane * 2] =
        make_uint2(*(uint32_t*)&o0, *(uint32_t*)&o1);
}

// ---------------------------------------------------------------------------
// fp16 tensor-core GEMM (m16n8k16) with ldmatrix fragment loads.
// A operands fp16 in gmem (raw 16B staging copies); weights fp32 (cvt at
// staging); C written fp16. 128x128 tile, BK=32, 8 warps (4x2).
// ---------------------------------------------------------------------------
__device__ __forceinline__ void mma_f16(float* c, const uint32_t* a,
                                        const uint32_t* b) {
    asm volatile(
        "mma.sync.aligned.m16n8k16.row.col.f32.f16.f16.f32 "
        "{%0,%1,%2,%3}, {%4,%5,%6,%7}, {%8,%9}, {%0,%1,%2,%3};"
        : "+f"(c[0]), "+f"(c[1]), "+f"(c[2]), "+f"(c[3])
        : "r"(a[0]), "r"(a[1]), "r"(a[2]), "r"(a[3]), "r"(b[0]), "r"(b[1]));
}
__device__ __forceinline__ uint32_t smem_u32(const void* p) {
    return (uint32_t)__cvta_generic_to_shared(p);
}
__device__ __forceinline__ void ldsm_x4(uint32_t* r, uint32_t addr) {
    asm volatile("ldmatrix.sync.aligned.m8n8.x4.shared.b16 {%0,%1,%2,%3}, [%4];"
                 : "=r"(r[0]), "=r"(r[1]), "=r"(r[2]), "=r"(r[3]) : "r"(addr));
}
__device__ __forceinline__ void ldsm_x4_trans(uint32_t* r, uint32_t addr) {
    asm volatile("ldmatrix.sync.aligned.m8n8.x4.trans.shared.b16 {%0,%1,%2,%3}, [%4];"
                 : "=r"(r[0]), "=r"(r[1]), "=r"(r[2]), "=r"(r[3]) : "r"(addr));
}

#define BM 128
#define BN 128
#define BK 32
#define APITCH 40    // halves per A row (32 used + 8 pad) = 80B
#define BPITCH 136   // halves per B row (128 used + 8 pad) = 272B

__device__ __forceinline__ void ldg_tile(
    const __half* __restrict__ A, const float* __restrict__ W,
    int K, int Cout, int kt, int row0, int col0, int M, int tid,
    uint4* Ar, float4* Br) {
    #pragma unroll
    for (int i = 0; i < 2; i++) {
        int lin = tid + i * 256;        // 0..511
        int r = lin >> 2, c8 = (lin & 3) << 3;   // 128 rows x 4 uint4
        int gr = row0 + r;
        Ar[i] = (gr < M) ? *(const uint4*)&A[(size_t)gr * K + kt + c8]
                         : make_uint4(0, 0, 0, 0);
    }
    #pragma unroll
    for (int i = 0; i < 4; i++) {
        int lin = tid + i * 256;
        int bk = lin >> 5, c4 = (lin & 31) << 2;
        Br[i] = *(const float4*)&W[(size_t)(kt + bk) * Cout + col0 + c4];
    }
}

__global__ void __launch_bounds__(256, 2)
gemm_tc_kernel(int a0_sel, const float* __restrict__ W0, int K0,
               int a1_sel, const float* __restrict__ W1, int K1,
               const float* __restrict__ bias, int c_sel,
               int M, int Cout, int relu,
               const float* __restrict__ Wb, const float* __restrict__ biasb,
               int cb_sel) {
    __shared__ __half As[BM * APITCH];
    __shared__ __half Bs[BK * BPITCH];

    int tid  = threadIdx.x;
    int wid  = tid >> 5, lane = tid & 31;
    int gid  = lane >> 2, tig = lane & 3;
    int wm   = wid & 3,  wn  = wid >> 2;
    int row0 = blockIdx.x * BM;
    int col0;
    if (Wb != nullptr) {             // dual-output: blockIdx.y picks W/bias/C
        col0 = 0;
        if (blockIdx.y == 1) { W0 = Wb; bias = biasb; c_sel = cb_sel; }
    } else {
        col0 = blockIdx.y * BN;
    }

    int lr  = lane & 7;
    int g1_ = (lane >> 3) & 1;
    int g2_ = lane >> 4;

    float acc[2][8][4];
    #pragma unroll
    for (int i = 0; i < 2; i++)
        #pragma unroll
        for (int j = 0; j < 8; j++)
            #pragma unroll
            for (int k = 0; k < 4; k++) acc[i][j][k] = 0.f;

    const __half* A0 = hbuf(a0_sel);
    const __half* A1 = (a1_sel < 0) ? nullptr : hbuf(a1_sel);
    int T0 = K0 >> 5;
    int T1 = (a1_sel < 0) ? 0 : (K1 >> 5);
    int T  = T0 + T1;

    uint4  Ar[2];
    float4 Br[4];
    ldg_tile(A0, W0, K0, Cout, 0, row0, col0, M, tid, Ar, Br);

    #pragma unroll 1
    for (int t = 0; t < T; t++) {
        // stage A: raw 16B copies (already fp16) — no conversion
        #pragma unroll
        for (int i = 0; i < 2; i++) {
            int lin = tid + i * 256;
            int r = lin >> 2, c8 = (lin & 3) << 3;
            *(uint4*)&As[r * APITCH + c8] = Ar[i];
        }
        // stage B [BK][BN]: fp32 weights -> fp16
        #pragma unroll
        for (int i = 0; i < 4; i++) {
            int lin = tid + i * 256;
            int bk = lin >> 5, c4 = (lin & 31) << 2;
            __half2 h0 = __floats2half2_rn(Br[i].x, Br[i].y);
            __half2 h1 = __floats2half2_rn(Br[i].z, Br[i].w);
            *(uint2*)&Bs[bk * BPITCH + c4] =
                make_uint2(*(uint32_t*)&h0, *(uint32_t*)&h1);
        }
        __syncthreads();

        if (t + 1 < T) {
            int tn_ = t + 1;
            const __half* A = (tn_ < T0) ? A0 : A1;
            const float*  W = (tn_ < T0) ? W0 : W1;
            int K  = (tn_ < T0) ? K0 : K1;
            int kt = (tn_ < T0) ? tn_ * BK : (tn_ - T0) * BK;
            ldg_tile(A, W, K, Cout, kt, row0, col0, M, tid, Ar, Br);
        }

        #pragma unroll
        for (int ks = 0; ks < 2; ks++) {
            int k0 = ks * 16;
            uint32_t af[2][4];
            #pragma unroll
            for (int mt = 0; mt < 2; mt++) {
                int row = wm * 32 + mt * 16 + lr + g1_ * 8;
                int col = k0 + g2_ * 8;
                ldsm_x4(af[mt], smem_u32(&As[row * APITCH + col]));
            }
            uint32_t bf[8][2];
            #pragma unroll
            for (int np = 0; np < 4; np++) {
                int row = k0 + lr + g1_ * 8;
                int col = wn * 64 + np * 16 + g2_ * 8;
                uint32_t tmp[4];
                ldsm_x4_trans(tmp, smem_u32(&Bs[row * BPITCH + col]));
                bf[np * 2    ][0] = tmp[0];
                bf[np * 2    ][1] = tmp[1];
                bf[np * 2 + 1][0] = tmp[2];
                bf[np * 2 + 1][1] = tmp[3];
            }
            #pragma unroll
            for (int mt = 0; mt < 2; mt++)
                #pragma unroll
                for (int nt = 0; nt < 8; nt++)
                    mma_f16(acc[mt][nt], af[mt], bf[nt]);
        }
        __syncthreads();
    }

    __half2* Ch = hout(c_sel);
    #pragma unroll
    for (int mt = 0; mt < 2; mt++) {
        #pragma unroll
        for (int half_ = 0; half_ < 2; half_++) {
            int r = row0 + wm * 32 + mt * 16 + gid + half_ * 8;
            if (r < M) {
                #pragma unroll
                for (int nt = 0; nt < 8; nt++) {
                    int c = col0 + wn * 64 + nt * 8 + tig * 2;
                    float v0 = acc[mt][nt][half_ * 2 + 0];
                    float v1 = acc[mt][nt][half_ * 2 + 1];
                    if (bias) { v0 += bias[c]; v1 += bias[c + 1]; }
                    if (relu) { v0 = fmaxf(v0, 0.f); v1 = fmaxf(v1, 0.f); }
                    Ch[((size_t)r * Cout + c) >> 1] = __floats2half2_rn(v0, v1);
                }
            }
        }
    }
}

// ---------------------------------------------------------------------------
// Graph segment boundaries via binary search over sorted batch (int32)
// ---------------------------------------------------------------------------
__global__ void gstart_kernel(const int* __restrict__ batch) {
    int g = blockIdx.x * blockDim.x + threadIdx.x;
    if (g > GG) return;
    int lo = 0, hi = NN;
    while (lo < hi) {
        int mid = (lo + hi) >> 1;
        if (batch[mid] < g) lo = mid + 1; else hi = mid;
    }
    g_gstart[g] = lo;
}

// ---------------------------------------------------------------------------
// Pool (mean over graph) + 2-layer MLP head. One 128-thread block per graph.
// h3[n] = agg3[n] + z3[n]  (both fp16; fp32 accumulation)
// ---------------------------------------------------------------------------
__global__ void pool_head_kernel(const float* __restrict__ W1,
                                 const float* __restrict__ b1,
                                 const float* __restrict__ W2,
                                 const float* __restrict__ b2,
                                 float* __restrict__ out) {
    int g = blockIdx.x;
    int c = threadIdx.x;  // 0..127
    int s = g_gstart[g];
    int e = g_gstart[g + 1];
    const __half* agg = (const __half*)g_aggh4;
    const __half* z3  = (const __half*)g_z3h4;
    float acc = 0.f;
    for (int n = s; n < e; n++)
        acc += __half2float(agg[(size_t)n * 128 + c]) +
               __half2float(z3[(size_t)n * 128 + c]);
    float cnt = (float)((e - s) > 1 ? (e - s) : 1);
    __shared__ float p[128];
    __shared__ float t[40];
    p[c] = acc / cnt;
    __syncthreads();
    if (c < 40) {
        float tt = b1[c];
        #pragma unroll 4
        for (int k = 0; k < 128; k++) tt += p[k] * W1[k * 40 + c];
        t[c] = tt;
    }
    __syncthreads();
    if (c < 10) {
        float o = b2[c];
        #pragma unroll
        for (int k = 0; k < 40; k++) o += t[k] * W2[k * 10 + c];
        out[g * 10 + c] = o;
    }
}

// ---------------------------------------------------------------------------
// Launch: ONLY kernel launches.
// ---------------------------------------------------------------------------
extern "C" void kernel_launch(void* const* d_in, const int* in_sizes, int n_in,
                              void* d_out, int out_size) {
    const float* x     = (const float*)d_in[0];
    const int*   ei    = (const int*)d_in[1];
    const int*   batch = (const int*)d_in[2];
    const float* Wr1 = (const float*)d_in[3];
    const float* br1 = (const float*)d_in[4];
    const float* Wo1 = (const float*)d_in[5];
    const float* Wr2 = (const float*)d_in[6];
    const float* br2 = (const float*)d_in[7];
    const float* Wo2 = (const float*)d_in[8];
    const float* Wr3 = (const float*)d_in[9];
    const float* br3 = (const float*)d_in[10];
    const float* Wo3 = (const float*)d_in[11];
    const float* W1  = (const float*)d_in[12];
    const float* b1  = (const float*)d_in[13];
    const float* W2  = (const float*)d_in[14];
    const float* b2  = (const float*)d_in[15];
    float* out = (float*)d_out;

    const int* srcp = ei;
    const int* dstp = ei + EE;

    const int EB = (EE + 255) / 256;
    const int AGGB = (NN * 32 + 255) / 256;
    dim3 g1((NN + 127) / 128, 1);
    dim3 g2((NN + 127) / 128, 2);

    // CSR build + x fp16 mirror
    zero_deg_kernel<<<(NN + 255) / 256, 256>>>();
    convert_x_kernel<<<(NN * 16 + 255) / 256, 256>>>(x);
    count_kernel<<<EB, 256>>>(dstp);
    block_reduce_kernel<<<SCAN_BLKS, 1024>>>();
    scan_bsums_kernel<<<1, 64>>>();
    block_scan_kernel<<<SCAN_BLKS, 1024>>>();
    fill_kernel<<<EB, 256>>>(srcp, dstp);
    gstart_kernel<<<1, 1024>>>(batch);

    // Layer 1: agg = A(x_h); h1 = relu(agg@Wr1 + x_h@Wo1 + br1)
    aggregate_h_kernel<<<AGGB, 256>>>(0);
    gemm_tc_kernel<<<g1, 256>>>(1, Wr1, 128, 0, Wo1, 128, br1, 2,
                                NN, 128, 1, nullptr, nullptr, 0);

    // Layer 2: agg = A(h1); h2 = relu(agg@Wr2 + h1@Wo2 + br2)
    aggregate_h_kernel<<<AGGB, 256>>>(2);
    gemm_tc_kernel<<<g2, 256>>>(1, Wr2, 128, 2, Wo2, 128, br2, 3,
                                NN, 256, 1, nullptr, nullptr, 0);

    // Layer 3 (matmul-first, dual-output): y3 = h2@Wr3; z3 = h2@Wo3 + br3
    gemm_tc_kernel<<<g2, 256>>>(3, Wr3, 256, -1, nullptr, 0, nullptr, 4,
                                NN, 128, 0, Wo3, br3, 5);

    // agg = A(y3), then pool + head
    aggregate_h_kernel<<<AGGB, 256>>>(4);
    pool_head_kernel<<<GG, 128>>>(W1, b1, W2, b2, out);
}